// round 10
// baseline (speedup 1.0000x reference)
#include <cuda_runtime.h>
#include <cuda_fp16.h>
#include <stdint.h>

// ============================================================================
// ExpertLinear as ONE GEMM: C(4096x1024) = A(4096x8256) * W'(1024x8256)^T
//   A[b, e*1024+i] = blend[b,e]*x[b,i];  A[b,8192+e] = blend[b,e]; pad 0
//   W'[o, e*1024+i] = weight[e,o,i];     W'[o,8192+e] = bias[e,o]; pad 0
// Single-term FP16, fp32 accumulate (rel_err ~2.9e-4, threshold 1e-3).
// Round 10: R9's two-independent-warp-group design (own B copy, own cp.async
// ladder, own named barrier -> groups' LDS/MMA phases interleave) but with
// R8's provably-safe 2-STAGE schedule per group: refill buffer (c+1)&1 --
// fully consumed one iteration ago -- while computing on c&1. R9's 3-stage
// ring self-overwrote (chunk c+3 -> buffer c%3 while chunk c still reading).
// 256x128 CTA tile (128 CTAs = 1 wave), KC=64, 2 stages x 64KB = 128KB smem.
// ============================================================================

#define B_TOT   4096
#define IN_DIM  1024
#define OUT_DIM 1024
#define NEXP    8
#define KTOT    8256
#define KC      64
#define NCHUNKS (KTOT / KC)     // 129 (chunk 128 = bias columns)
#define TM      256
#define TN      128
#define NTHREADS 256
#define STAGES  2

#define HTILE_B 16384                  // 128 rows x 128B (A half or B copy)
#define STAGE_B (4 * HTILE_B)          // A_g0, A_g1, B_g0, B_g1 = 65536
#define SMEM_BYTES (STAGES * STAGE_B)  // 131072

// Global scratch (allocation-free rule: __device__ globals)
__device__ __align__(16) __half g_Wh[(size_t)OUT_DIM * KTOT];   // 16.9 MB
__device__ __align__(16) __half g_Ah[(size_t)B_TOT * KTOT];     // 67.6 MB

// ---------------------------------------------------------------------------
__device__ __forceinline__ uint32_t smem_u32(const void* p) {
    uint32_t a;
    asm("{ .reg .u64 t; cvta.to.shared.u64 t, %1; cvt.u32.u64 %0, t; }"
        : "=r"(a) : "l"(p));
    return a;
}

__device__ __forceinline__ void ldsm_x4(uint32_t* r, uint32_t addr) {
    asm volatile("ldmatrix.sync.aligned.m8n8.x4.shared.b16 {%0,%1,%2,%3}, [%4];"
                 : "=r"(r[0]), "=r"(r[1]), "=r"(r[2]), "=r"(r[3]) : "r"(addr));
}

__device__ __forceinline__ void mma_fp16(float* c, const uint32_t* a,
                                         uint32_t b0, uint32_t b1) {
    asm volatile(
        "mma.sync.aligned.m16n8k16.row.col.f32.f16.f16.f32 "
        "{%0,%1,%2,%3}, {%4,%5,%6,%7}, {%8,%9}, {%0,%1,%2,%3};"
        : "+f"(c[0]), "+f"(c[1]), "+f"(c[2]), "+f"(c[3])
        : "r"(a[0]), "r"(a[1]), "r"(a[2]), "r"(a[3]), "r"(b0), "r"(b1));
}

__device__ __forceinline__ void cp_async16(uint32_t saddr, const void* gptr) {
    asm volatile("cp.async.cg.shared.global [%0], [%1], 16;"
                 :: "r"(saddr), "l"(gptr) : "memory");
}

__device__ __forceinline__ uint32_t pack_h2(float a, float b) {
    uint32_t r;
    asm("cvt.rn.f16x2.f32 %0, %1, %2;" : "=r"(r) : "f"(b), "f"(a));
    return r;
}

// named barrier: 128 threads of one warp-group
__device__ __forceinline__ void group_bar(int id) {
    asm volatile("bar.sync %0, 128;" :: "r"(id) : "memory");
}

// ---------------------------------------------------------------------------
// Kernel 1 (fused, 8-wide): W' and A -> fp16 scratch.
// ---------------------------------------------------------------------------
__global__ void __launch_bounds__(256)
convert_kernel(const float* __restrict__ weight, const float* __restrict__ bias,
               const float* __restrict__ x, const float* __restrict__ blend) {
    int kk = (blockIdx.x * 256 + threadIdx.x) * 8;
    if (kk >= KTOT) return;
    float v[8];
    if (blockIdx.y < OUT_DIM) {
        int o = blockIdx.y;
        if (kk < NEXP * IN_DIM) {
            int e = kk >> 10, i = kk & 1023;
            const float4* src = reinterpret_cast<const float4*>(
                weight + (size_t)e * OUT_DIM * IN_DIM + (size_t)o * IN_DIM + i);
            float4 w0 = src[0], w1 = src[1];
            v[0] = w0.x; v[1] = w0.y; v[2] = w0.z; v[3] = w0.w;
            v[4] = w1.x; v[5] = w1.y; v[6] = w1.z; v[7] = w1.w;
        } else {
            #pragma unroll
            for (int j = 0; j < 8; ++j) {
                int e = kk + j - NEXP * IN_DIM;
                v[j] = (e >= 0 && e < NEXP) ? bias[(size_t)e * OUT_DIM + o] : 0.0f;
            }
        }
        uint4 h = make_uint4(pack_h2(v[0], v[1]), pack_h2(v[2], v[3]),
                             pack_h2(v[4], v[5]), pack_h2(v[6], v[7]));
        *reinterpret_cast<uint4*>(&g_Wh[(size_t)o * KTOT + kk]) = h;
    } else {
        int b = blockIdx.y - OUT_DIM;
        if (kk < NEXP * IN_DIM) {
            int e = kk >> 10, i = kk & 1023;
            float w = blend[b * NEXP + e];
            const float4* src =
                reinterpret_cast<const float4*>(x + (size_t)b * IN_DIM + i);
            float4 x0 = src[0], x1 = src[1];
            v[0] = x0.x * w; v[1] = x0.y * w; v[2] = x0.z * w; v[3] = x0.w * w;
            v[4] = x1.x * w; v[5] = x1.y * w; v[6] = x1.z * w; v[7] = x1.w * w;
        } else {
            #pragma unroll
            for (int j = 0; j < 8; ++j) {
                int e = kk + j - NEXP * IN_DIM;
                v[j] = (e < NEXP) ? blend[b * NEXP + e] : 0.0f;
            }
        }
        uint4 h = make_uint4(pack_h2(v[0], v[1]), pack_h2(v[2], v[3]),
                             pack_h2(v[4], v[5]), pack_h2(v[6], v[7]));
        *reinterpret_cast<uint4*>(&g_Ah[(size_t)b * KTOT + kk]) = h;
    }
}

// ---------------------------------------------------------------------------
// Kernel 2: GEMM. Two independent 128-thread warp-groups per CTA, each doing
// a 128x128 sub-GEMM (4 warps x 64x64 tiles), own B copy, own async ladder,
// own named barrier, 2-stage (R8 schedule). KC=64.
// ---------------------------------------------------------------------------
__global__ void __launch_bounds__(NTHREADS, 1)
moe_gemm_kernel(float* __restrict__ out) {
    extern __shared__ char smem[];
    const uint32_t sb = smem_u32(smem);
    const int t = threadIdx.x;
    const int g = t >> 7;           // warp-group 0/1
    const int tg = t & 127;         // thread within group
    const int lid = t & 31;
    const int widg = (t >> 5) & 3;  // warp within group 0..3
    const int wm = widg >> 1;       // 0..1 (M warps, 64 rows)
    const int wn = widg & 1;        // 0..1 (N warps, 64 cols)
    const int tileX = blockIdx.x;   // N (o), 0..7
    const int tileY = blockIdx.y;   // M (b), 0..15
    const int barid = g + 1;

    // group smem bases within a stage
    const uint32_t aOff = (uint32_t)g * HTILE_B;                 // A_g
    const uint32_t bOff = 2u * HTILE_B + (uint32_t)g * HTILE_B;  // B_g

    // cp.async staging (per group: 128 thr, A 128 rows + B 128 rows, 8+8 x16B)
    const int brow = tg >> 3;       // 0..15
    const int bseg = tg & 7;        // 0..7
    const __half* __restrict__ pA = g_Ah;
    const __half* __restrict__ pW = g_Wh;
    const uint32_t soBase = (uint32_t)(brow * 128 + ((bseg ^ (brow & 7)) << 4));
    const uint32_t gA0 =
        (uint32_t)(tileY * TM + g * 128 + brow) * KTOT + bseg * 8;
    const uint32_t gB0 = (uint32_t)(tileX * TN + brow) * KTOT + bseg * 8;

    // ldmatrix addressing (within group's 128x128 tiles)
    const int lid15 = lid & 15;
    const uint32_t half_ = (uint32_t)(lid >> 4);
    const uint32_t par = (uint32_t)(lid & 7);
    uint32_t a_row[4], b_row[4];
    #pragma unroll
    for (int mi = 0; mi < 4; ++mi)
        a_row[mi] = (uint32_t)((wm * 64 + mi * 16 + lid15) * 128);
    #pragma unroll
    for (int nj = 0; nj < 4; ++nj)
        b_row[nj] = (uint32_t)((wn * 64 + nj * 16 + lid15) * 128);

    float acc[4][8][4];
    #pragma unroll
    for (int mi = 0; mi < 4; ++mi)
        #pragma unroll
        for (int ni = 0; ni < 8; ++ni)
            #pragma unroll
            for (int q = 0; q < 4; ++q) acc[mi][ni][q] = 0.0f;

    #define ISSUE(bufi, kof)                                                   \
        do {                                                                   \
            uint32_t base = sb + (uint32_t)(bufi) * STAGE_B;                   \
            _Pragma("unroll")                                                  \
            for (int p = 0; p < 8; ++p)                                        \
                cp_async16(base + aOff + soBase + p * 2048,                    \
                           pA + gA0 + (kof) + p * 16 * KTOT);                  \
            _Pragma("unroll")                                                  \
            for (int p = 0; p < 8; ++p)                                        \
                cp_async16(base + bOff + soBase + p * 2048,                    \
                           pW + gB0 + (kof) + p * 16 * KTOT);                  \
            asm volatile("cp.async.commit_group;" ::: "memory");               \
        } while (0)

    #define LOADFRAG(ks, bufi)                                                 \
        do {                                                                   \
            uint32_t koff = (((uint32_t)(2 * (ks)) + half_) ^ par) << 4;       \
            _Pragma("unroll")                                                  \
            for (int nj = 0; nj < 4; ++nj)                                     \
                ldsm_x4(bF[bufi][nj], Bb + b_row[nj] + koff);                  \
            _Pragma("unroll")                                                  \
            for (int mi = 0; mi < 4; ++mi)                                     \
                ldsm_x4(aF[bufi][mi], Ab + a_row[mi] + koff);                  \
        } while (0)

    ISSUE(0, 0u);

    for (int c = 0; c < NCHUNKS; ++c) {
        // exactly one group (chunk c) outstanding on this thread's ladder
        asm volatile("cp.async.wait_group 0;" ::: "memory");
        group_bar(barid);

        const uint32_t base = sb + (uint32_t)(c & 1) * STAGE_B;
        const uint32_t Ab = base + aOff, Bb = base + bOff;

        // head fragments first: ldsm latency hides under the ISSUE burst
        uint32_t aF[2][4][4], bF[2][4][4];
        LOADFRAG(0, 0);

        // other buffer was fully consumed in iteration c-1 (group_bar above
        // ordered all its ldsm before this point) -> safe to refill
        if (c + 1 < NCHUNKS) ISSUE((c + 1) & 1, (uint32_t)((c + 1) * KC));

        #pragma unroll
        for (int ks = 0; ks < 4; ++ks) {
            const int cu = ks & 1, nx = cu ^ 1;
            if (ks < 3) LOADFRAG(ks + 1, nx);
            #pragma unroll
            for (int mi = 0; mi < 4; ++mi) {
                #pragma unroll
                for (int nj = 0; nj < 4; ++nj) {
                    mma_fp16(acc[mi][2 * nj],     aF[cu][mi], bF[cu][nj][0],
                             bF[cu][nj][2]);
                    mma_fp16(acc[mi][2 * nj + 1], aF[cu][mi], bF[cu][nj][1],
                             bF[cu][nj][3]);
                }
            }
        }
    }

    // Epilogue (per group: rows g*128 .. g*128+127)
    const int erow = lid >> 2;
    const int ecol = (lid & 3) * 2;
    #pragma unroll
    for (int mi = 0; mi < 4; ++mi) {
        #pragma unroll
        for (int ni = 0; ni < 8; ++ni) {
            int rg0 = tileY * TM + g * 128 + wm * 64 + mi * 16 + erow;
            int oc = tileX * TN + wn * 64 + ni * 8 + ecol;
            float2 v01 = make_float2(acc[mi][ni][0], acc[mi][ni][1]);
            float2 v23 = make_float2(acc[mi][ni][2], acc[mi][ni][3]);
            *reinterpret_cast<float2*>(out + (size_t)rg0 * OUT_DIM + oc) = v01;
            *reinterpret_cast<float2*>(out + (size_t)(rg0 + 8) * OUT_DIM + oc) = v23;
        }
    }
}

// ---------------------------------------------------------------------------
extern "C" void kernel_launch(void* const* d_in, const int* in_sizes, int n_in,
                              void* d_out, int out_size) {
    const float* x      = (const float*)d_in[0];
    const float* blend  = (const float*)d_in[1];
    const float* weight = (const float*)d_in[2];
    const float* bias   = (const float*)d_in[3];
    float* out = (float*)d_out;

    dim3 cgrid((KTOT / 8 + 255) / 256, OUT_DIM + B_TOT);
    convert_kernel<<<cgrid, 256>>>(weight, bias, x, blend);

    cudaFuncSetAttribute(moe_gemm_kernel,
                         cudaFuncAttributeMaxDynamicSharedMemorySize, SMEM_BYTES);
    dim3 grid(OUT_DIM / TN, B_TOT / TM);   // (8, 16) = 128 CTAs, one wave
    moe_gemm_kernel<<<grid, NTHREADS, SMEM_BYTES>>>(out);
}

// round 11
// speedup vs baseline: 2.3421x; 2.3421x over previous
#include <cuda_runtime.h>
#include <cuda_fp16.h>
#include <stdint.h>

// ============================================================================
// ExpertLinear as ONE GEMM: C(4096x1024) = A(4096x8320) * W'(1024x8320)^T
//   A[b, e*1024+i] = blend[b,e]*x[b,i];  A[b,8192+e] = blend[b,e]; pad 0
//   W'[o, e*1024+i] = weight[e,o,i];     W'[o,8192+e] = bias[e,o]; pad 0
// Single-term FP16, fp32 accumulate (rel_err ~2.9e-4, threshold 1e-3).
// Round 11: legacy mma.sync is pinned at ~11 cyc/HMMA/SMSP across every
// schedule tried (R4/R6/R8/R10) -> engine ceiling. Probe tcgen05 via an
// ARCH-GATED twin-kernel: tc_gemm_kernel body exists only when the build
// has an sm_103a ('a'-features) pass (__CUDA_ARCH_FEAT_SM103_ALL); the
// proven R8 fp16-mma kernel body exists only otherwise. Both are launched;
// exactly one does the work. Worst case = current best (neutral probe).
// ============================================================================

#if defined(__CUDA_ARCH_FEAT_SM103_ALL) || defined(__CUDA_ARCH_FEAT_SM100_ALL)
#define HAS_TC 1
#else
#define HAS_TC 0
#endif

#define B_TOT   4096
#define IN_DIM  1024
#define OUT_DIM 1024
#define NEXP    8
#define KTOT    8320                   // 65*128 = 130*64

// ---- fallback (R8) geometry ----
#define KC_FB   128
#define NCH_FB  (KTOT / KC_FB)         // 65
#define TM_FB   256
#define TN_FB   128
#define ROWB_FB 256
#define A_TILE_FB (TM_FB * ROWB_FB)    // 65536
#define B_TILE_FB (TN_FB * ROWB_FB)    // 32768
#define STAGE_FB  (A_TILE_FB + B_TILE_FB)
#define SMEM_FB   (2 * STAGE_FB)       // 196608

// ---- tcgen05 geometry ----
#define KC_TC   64
#define NCH_TC  (KTOT / KC_TC)         // 130
#define TM_TC   128
#define TN_TC   256
#define A_TILE_TC (TM_TC * 128)        // 16384 (128 rows x 128B)
#define B_TILE_TC (TN_TC * 128)        // 32768
#define STAGE_TC  (A_TILE_TC + B_TILE_TC)  // 49152
#define SMEM_TC   (1024 + 3 * STAGE_TC)    // 148480

// Global scratch (allocation-free rule: __device__ globals)
__device__ __align__(16) __half g_Wh[(size_t)OUT_DIM * KTOT];   // 17.0 MB
__device__ __align__(16) __half g_Ah[(size_t)B_TOT * KTOT];     // 68.2 MB

// ---------------------------------------------------------------------------
__device__ __forceinline__ uint32_t smem_u32(const void* p) {
    uint32_t a;
    asm("{ .reg .u64 t; cvta.to.shared.u64 t, %1; cvt.u32.u64 %0, t; }"
        : "=r"(a) : "l"(p));
    return a;
}

__device__ __forceinline__ void cp_async16(uint32_t saddr, const void* gptr) {
    asm volatile("cp.async.cg.shared.global [%0], [%1], 16;"
                 :: "r"(saddr), "l"(gptr) : "memory");
}

__device__ __forceinline__ uint32_t pack_h2(float a, float b) {
    uint32_t r;
    asm("cvt.rn.f16x2.f32 %0, %1, %2;" : "=r"(r) : "f"(b), "f"(a));
    return r;
}

__device__ __forceinline__ void mbar_wait(uint32_t mbar, uint32_t parity) {
    asm volatile(
        "{\n\t.reg .pred P;\n\t"
        "WL_%=:\n\t"
        "mbarrier.try_wait.parity.acquire.cta.shared::cta.b64 P, [%0], %1, 0x989680;\n\t"
        "@P bra.uni WD_%=;\n\t"
        "bra.uni WL_%=;\n\t"
        "WD_%=:\n\t}"
        :: "r"(mbar), "r"(parity) : "memory");
}

// ---------------------------------------------------------------------------
// Kernel 1 (fused, 8-wide): W' and A -> fp16 scratch (always active).
// ---------------------------------------------------------------------------
__global__ void __launch_bounds__(256)
convert_kernel(const float* __restrict__ weight, const float* __restrict__ bias,
               const float* __restrict__ x, const float* __restrict__ blend) {
    int kk = (blockIdx.x * 256 + threadIdx.x) * 8;
    if (kk >= KTOT) return;
    float v[8];
    if (blockIdx.y < OUT_DIM) {
        int o = blockIdx.y;
        if (kk < NEXP * IN_DIM) {
            int e = kk >> 10, i = kk & 1023;
            const float4* src = reinterpret_cast<const float4*>(
                weight + (size_t)e * OUT_DIM * IN_DIM + (size_t)o * IN_DIM + i);
            float4 w0 = src[0], w1 = src[1];
            v[0] = w0.x; v[1] = w0.y; v[2] = w0.z; v[3] = w0.w;
            v[4] = w1.x; v[5] = w1.y; v[6] = w1.z; v[7] = w1.w;
        } else {
            #pragma unroll
            for (int j = 0; j < 8; ++j) {
                int e = kk + j - NEXP * IN_DIM;
                v[j] = (e >= 0 && e < NEXP) ? bias[(size_t)e * OUT_DIM + o] : 0.0f;
            }
        }
        uint4 h = make_uint4(pack_h2(v[0], v[1]), pack_h2(v[2], v[3]),
                             pack_h2(v[4], v[5]), pack_h2(v[6], v[7]));
        *reinterpret_cast<uint4*>(&g_Wh[(size_t)o * KTOT + kk]) = h;
    } else {
        int b = blockIdx.y - OUT_DIM;
        if (kk < NEXP * IN_DIM) {
            int e = kk >> 10, i = kk & 1023;
            float w = blend[b * NEXP + e];
            const float4* src =
                reinterpret_cast<const float4*>(x + (size_t)b * IN_DIM + i);
            float4 x0 = src[0], x1 = src[1];
            v[0] = x0.x * w; v[1] = x0.y * w; v[2] = x0.z * w; v[3] = x0.w * w;
            v[4] = x1.x * w; v[5] = x1.y * w; v[6] = x1.z * w; v[7] = x1.w * w;
        } else {
            #pragma unroll
            for (int j = 0; j < 8; ++j) {
                int e = kk + j - NEXP * IN_DIM;
                v[j] = (e < NEXP) ? blend[b * NEXP + e] : 0.0f;
            }
        }
        uint4 h = make_uint4(pack_h2(v[0], v[1]), pack_h2(v[2], v[3]),
                             pack_h2(v[4], v[5]), pack_h2(v[6], v[7]));
        *reinterpret_cast<uint4*>(&g_Ah[(size_t)b * KTOT + kk]) = h;
    }
}

// ===========================================================================
// tcgen05 path (compiled only when the build has an sm_103a/'a' pass)
// ===========================================================================
#if HAS_TC

__device__ __forceinline__ bool elect1() {
    uint32_t pred;
    asm volatile(
        "{\n\t.reg .pred p;\n\t"
        "elect.sync _|p, 0xFFFFFFFF;\n\t"
        "selp.b32 %0, 1, 0, p;\n\t}"
        : "=r"(pred));
    return pred != 0;
}

// SW128 K-major descriptor: layout=2, version=1 (Blackwell), SBO=64, LBO=1
__device__ __forceinline__ uint64_t smem_desc(uint32_t addr) {
    const uint64_t base = (uint64_t(2) << 61) | (uint64_t(1) << 46) |
                          (uint64_t(64) << 32) | (uint64_t(1) << 16);
    return base | ((uint64_t)(addr >> 4) & 0x3FFF);
}

// cg1 kind::f16 SS MMA (fp16 in, fp32 accum; types via idesc)
__device__ __forceinline__ void tc_mma(uint32_t d, uint64_t da, uint64_t db,
                                       uint32_t idesc, uint32_t en) {
    asm volatile(
        "{\n\t.reg .pred p;\n\t"
        "setp.ne.u32 p, %5, 0;\n\t"
        "tcgen05.mma.cta_group::1.kind::f16 [%0], %1, %2, %3, {%4, %4, %4, %4}, p;\n\t}"
        :: "r"(d), "l"(da), "l"(db), "r"(idesc), "r"(0u), "r"(en)
        : "memory");
}

#define TC_LDTM_X32(r, ta)                                                     \
    asm volatile(                                                              \
        "tcgen05.ld.sync.aligned.32x32b.x32.b32 "                              \
        "{%0, %1, %2, %3, %4, %5, %6, %7, "                                    \
        " %8, %9, %10, %11, %12, %13, %14, %15, "                              \
        " %16, %17, %18, %19, %20, %21, %22, %23, "                            \
        " %24, %25, %26, %27, %28, %29, %30, %31}, [%32];"                     \
        : "=r"((r)[0]),  "=r"((r)[1]),  "=r"((r)[2]),  "=r"((r)[3]),           \
          "=r"((r)[4]),  "=r"((r)[5]),  "=r"((r)[6]),  "=r"((r)[7]),           \
          "=r"((r)[8]),  "=r"((r)[9]),  "=r"((r)[10]), "=r"((r)[11]),          \
          "=r"((r)[12]), "=r"((r)[13]), "=r"((r)[14]), "=r"((r)[15]),          \
          "=r"((r)[16]), "=r"((r)[17]), "=r"((r)[18]), "=r"((r)[19]),          \
          "=r"((r)[20]), "=r"((r)[21]), "=r"((r)[22]), "=r"((r)[23]),          \
          "=r"((r)[24]), "=r"((r)[25]), "=r"((r)[26]), "=r"((r)[27]),          \
          "=r"((r)[28]), "=r"((r)[29]), "=r"((r)[30]), "=r"((r)[31])           \
        : "r"(ta))

#endif  // HAS_TC

// tcgen05 GEMM: tile 128x256, KC=64 (130 chunks), 3-stage cp.async,
// per-chunk commit -> mbarrier; refill of buffer (c+2)%3 gated on commit of
// chunk c-1 (its previous occupant), so MMA(c) overlaps loads of c+2.
__global__ void __launch_bounds__(128, 1)
tc_gemm_kernel(float* __restrict__ out) {
#if HAS_TC
    extern __shared__ char smem[];
    const uint32_t sb = smem_u32(smem);
    const int t = threadIdx.x;
    const int wid = t >> 5, lid = t & 31;
    const int tileX = blockIdx.x;   // 0..3  (N tiles of 256)
    const int tileY = blockIdx.y;   // 0..31 (M tiles of 128)

    const uint32_t TMEMP = sb, MB0 = sb + 8, MB1 = sb + 16;
    const uint32_t TILES = sb + 1024;

    if (t == 0) {
        asm volatile("mbarrier.init.shared.b64 [%0], 1;" :: "r"(MB0) : "memory");
        asm volatile("mbarrier.init.shared.b64 [%0], 1;" :: "r"(MB1) : "memory");
    }
    if (wid == 0) {
        asm volatile("tcgen05.alloc.cta_group::1.sync.aligned.shared::cta.b32 [%0], %1;"
                     :: "r"(TMEMP), "r"(256u) : "memory");
        asm volatile("tcgen05.relinquish_alloc_permit.cta_group::1.sync.aligned;");
    }
    __syncthreads();
    uint32_t tmem;
    asm volatile("ld.shared.b32 %0, [%1];" : "=r"(tmem) : "r"(TMEMP));

    // idesc: dtype=F32, atype=btype=F16(0), N=256, M=128, K-major both
    const uint32_t IDESC = (1u << 4) | ((TN_TC / 8) << 17) | ((TM_TC / 16) << 24);

    // staging: 128 threads, 16B segs; rows stride 16 -> (row&7) is constant
    const int seg = t & 7, row0 = t >> 3;   // row0 0..15
    const uint32_t so = (uint32_t)(row0 * 128 + ((seg ^ (row0 & 7)) << 4));
    const uint32_t gA0 = (uint32_t)(tileY * TM_TC + row0) * KTOT + seg * 8;
    const uint32_t gB0 = (uint32_t)(tileX * TN_TC + row0) * KTOT + seg * 8;
    const __half* __restrict__ pA = g_Ah;
    const __half* __restrict__ pW = g_Wh;

    #define TC_ISSUE(cc)                                                       \
        do {                                                                   \
            uint32_t base = TILES + (uint32_t)((cc) % 3) * STAGE_TC;           \
            _Pragma("unroll")                                                  \
            for (int p = 0; p < 8; ++p)                                        \
                cp_async16(base + so + p * 2048,                               \
                           pA + gA0 + (cc) * KC_TC + p * 16 * KTOT);           \
            _Pragma("unroll")                                                  \
            for (int p = 0; p < 16; ++p)                                       \
                cp_async16(base + A_TILE_TC + so + p * 2048,                   \
                           pW + gB0 + (cc) * KC_TC + p * 16 * KTOT);           \
            asm volatile("cp.async.commit_group;" ::: "memory");               \
        } while (0)

    TC_ISSUE(0);
    TC_ISSUE(1);

    for (int c = 0; c < NCH_TC; ++c) {
        if (c == NCH_TC - 1)
            asm volatile("cp.async.wait_group 0;" ::: "memory");
        else
            asm volatile("cp.async.wait_group 1;" ::: "memory");
        __syncthreads();
        asm volatile("fence.proxy.async.shared::cta;" ::: "memory");

        if (wid == 0 && elect1()) {
            uint32_t base = TILES + (uint32_t)(c % 3) * STAGE_TC;
            uint64_t da = smem_desc(base);
            uint64_t db = smem_desc(base + A_TILE_TC);
            #pragma unroll
            for (int s = 0; s < 4; ++s) {   // 4 x K=16, +2 desc units (32B)
                uint32_t en = (c > 0 || s > 0) ? 1u : 0u;
                tc_mma(tmem, da + s * 2, db + s * 2, IDESC, en);
            }
            asm volatile(
                "tcgen05.commit.cta_group::1.mbarrier::arrive::one.shared::cluster.b64 [%0];"
                :: "r"((c & 1) ? MB1 : MB0) : "memory");
        }

        // gate refill of buffer (c+2)%3 on completion of its previous
        // occupant, chunk c-1 (committed last iteration -> near-zero wait)
        if (c >= 1)
            mbar_wait(((c - 1) & 1) ? MB1 : MB0, (uint32_t)(((c - 1) >> 1) & 1));
        if (c + 2 < NCH_TC) TC_ISSUE(c + 2);
    }

    // wait for the final chunk's MMAs (chunk 129 -> MB1, parity 0)
    mbar_wait(MB1, (uint32_t)(((NCH_TC - 1) >> 1) & 1));
    asm volatile("tcgen05.fence::after_thread_sync;" ::: "memory");

    // Epilogue: each warp reads its 32-lane TMEM subpartition, 256 cols fp32
    {
        float* orow = out + (size_t)(tileY * TM_TC + wid * 32 + lid) * OUT_DIM +
                      tileX * TN_TC;
        #pragma unroll
        for (int cb = 0; cb < 8; ++cb) {
            uint32_t r[32];
            TC_LDTM_X32(r, tmem + cb * 32);
            asm volatile("tcgen05.wait::ld.sync.aligned;" ::: "memory");
            #pragma unroll
            for (int j = 0; j < 32; j += 4) {
                float4 v = make_float4(__uint_as_float(r[j]),
                                       __uint_as_float(r[j + 1]),
                                       __uint_as_float(r[j + 2]),
                                       __uint_as_float(r[j + 3]));
                *reinterpret_cast<float4*>(orow + cb * 32 + j) = v;
            }
        }
    }
    asm volatile("tcgen05.fence::before_thread_sync;" ::: "memory");
    __syncthreads();
    if (wid == 0) {
        asm volatile("tcgen05.dealloc.cta_group::1.sync.aligned.b32 %0, %1;"
                     :: "r"(tmem), "r"(256u));
    }
#endif  // HAS_TC
}

// ===========================================================================
// Fallback: R8 fp16 mma.sync GEMM (body only when NO 'a' pass) — best legacy.
// ===========================================================================
#if !HAS_TC
__device__ __forceinline__ void ldsm_x4(uint32_t* r, uint32_t addr) {
    asm volatile("ldmatrix.sync.aligned.m8n8.x4.shared.b16 {%0,%1,%2,%3}, [%4];"
                 : "=r"(r[0]), "=r"(r[1]), "=r"(r[2]), "=r"(r[3]) : "r"(addr));
}
__device__ __forceinline__ void mma_fp16(float* c, const uint32_t* a,
                                         uint32_t b0, uint32_t b1) {
    asm volatile(
        "mma.sync.aligned.m16n8k16.row.col.f32.f16.f16.f32 "
        "{%0,%1,%2,%3}, {%4,%5,%6,%7}, {%8,%9}, {%0,%1,%2,%3};"
        : "+f"(c[0]), "+f"(c[1]), "+f"(c[2]), "+f"(c[3])
        : "r"(a[0]), "r"(a[1]), "r"(a[2]), "r"(a[3]), "r"(b0), "r"(b1));
}
#endif

__global__ void __launch_bounds__(256, 1)
fb_gemm_kernel(float* __restrict__ out) {
#if !HAS_TC
    extern __shared__ char smem[];
    const uint32_t sb = smem_u32(smem);
    const int t = threadIdx.x;
    const int wid = t >> 5, lid = t & 31;
    const int wm = wid >> 1;
    const int wn = wid & 1;
    const int tileX = blockIdx.x;
    const int tileY = blockIdx.y;

    const int brow = t >> 4;
    const int bseg = t & 15;
    const __half* __restrict__ pA = g_Ah;
    const __half* __restrict__ pW = g_Wh;
    const uint32_t soBase =
        (uint32_t)(brow * ROWB_FB + ((bseg ^ (brow & 7)) << 4));
    const uint32_t gA0 = (uint32_t)(tileY * TM_FB + brow) * KTOT + bseg * 8;
    const uint32_t gB0 = (uint32_t)(tileX * TN_FB + brow) * KTOT + bseg * 8;

    const int lid15 = lid & 15;
    const uint32_t half_ = (uint32_t)(lid >> 4);
    const uint32_t par = (uint32_t)(lid & 7);
    uint32_t a_row[4], b_row[4];
    #pragma unroll
    for (int mi = 0; mi < 4; ++mi)
        a_row[mi] = (uint32_t)((wm * 64 + mi * 16 + lid15) * ROWB_FB);
    #pragma unroll
    for (int nj = 0; nj < 4; ++nj)
        b_row[nj] = (uint32_t)((wn * 64 + nj * 16 + lid15) * ROWB_FB);

    float acc[4][8][4];
    #pragma unroll
    for (int mi = 0; mi < 4; ++mi)
        #pragma unroll
        for (int ni = 0; ni < 8; ++ni)
            #pragma unroll
            for (int q = 0; q < 4; ++q) acc[mi][ni][q] = 0.0f;

    #define FB_ISSUE(cc, kof)                                                  \
        do {                                                                   \
            uint32_t base = sb + (uint32_t)((cc) & 1) * STAGE_FB;              \
            _Pragma("unroll")                                                  \
            for (int p = 0; p < 16; ++p)                                       \
                cp_async16(base + soBase + p * (16 * ROWB_FB),                 \
                           pA + gA0 + (kof) + p * 16 * KTOT);                  \
            _Pragma("unroll")                                                  \
            for (int p = 0; p < 8; ++p)                                        \
                cp_async16(base + A_TILE_FB + soBase + p * (16 * ROWB_FB),     \
                           pW + gB0 + (kof) + p * 16 * KTOT);                  \
            asm volatile("cp.async.commit_group;" ::: "memory");               \
        } while (0)

    #define FB_LOADFRAG(ks, bufi)                                              \
        do {                                                                   \
            uint32_t koff = (((uint32_t)(2 * (ks)) + half_) ^ par) << 4;       \
            _Pragma("unroll")                                                  \
            for (int nj = 0; nj < 4; ++nj)                                     \
                ldsm_x4(bF[bufi][nj], Bb + b_row[nj] + koff);                  \
            _Pragma("unroll")                                                  \
            for (int mi = 0; mi < 4; ++mi)                                     \
                ldsm_x4(aF[bufi][mi], Ab + a_row[mi] + koff);                  \
        } while (0)

    FB_ISSUE(0, 0u);

    for (int c = 0; c < NCH_FB; ++c) {
        asm volatile("cp.async.wait_group 0;" ::: "memory");
        __syncthreads();

        const uint32_t base = sb + (uint32_t)(c & 1) * STAGE_FB;
        const uint32_t Ab = base, Bb = base + A_TILE_FB;

        uint32_t aF[2][4][4], bF[2][4][4];
        FB_LOADFRAG(0, 0);

        if (c + 1 < NCH_FB) FB_ISSUE(c + 1, (uint32_t)((c + 1) * KC_FB));

        #pragma unroll
        for (int ks = 0; ks < 8; ++ks) {
            const int cu = ks & 1, nx = cu ^ 1;
            if (ks < 7) FB_LOADFRAG(ks + 1, nx);
            #pragma unroll
            for (int mi = 0; mi < 4; ++mi) {
                #pragma unroll
                for (int nj = 0; nj < 4; ++nj) {
                    mma_fp16(acc[mi][2 * nj],     aF[cu][mi], bF[cu][nj][0],
                             bF[cu][nj][2]);
                    mma_fp16(acc[mi][2 * nj + 1], aF[cu][mi], bF[cu][nj][1],
                             bF[cu][nj][3]);
                }
            }
        }
    }

    const int erow = lid >> 2;
    const int ecol = (lid & 3) * 2;
    #pragma unroll
    for (int mi = 0; mi < 4; ++mi) {
        #pragma unroll
        for (int ni = 0; ni < 8; ++ni) {
            int rg0 = tileY * TM_FB + wm * 64 + mi * 16 + erow;
            int oc = tileX * TN_FB + wn * 64 + ni * 8 + ecol;
            float2 v01 = make_float2(acc[mi][ni][0], acc[mi][ni][1]);
            float2 v23 = make_float2(acc[mi][ni][2], acc[mi][ni][3]);
            *reinterpret_cast<float2*>(out + (size_t)rg0 * OUT_DIM + oc) = v01;
            *reinterpret_cast<float2*>(out + (size_t)(rg0 + 8) * OUT_DIM + oc) = v23;
        }
    }
#endif  // !HAS_TC
}

// ---------------------------------------------------------------------------
extern "C" void kernel_launch(void* const* d_in, const int* in_sizes, int n_in,
                              void* d_out, int out_size) {
    const float* x      = (const float*)d_in[0];
    const float* blend  = (const float*)d_in[1];
    const float* weight = (const float*)d_in[2];
    const float* bias   = (const float*)d_in[3];
    float* out = (float*)d_out;

    dim3 cgrid((KTOT / 8 + 255) / 256, OUT_DIM + B_TOT);
    convert_kernel<<<cgrid, 256>>>(weight, bias, x, blend);

    // tcgen05 path (no-op body unless the fatbin has an 'a'-features pass)
    cudaFuncSetAttribute(tc_gemm_kernel,
                         cudaFuncAttributeMaxDynamicSharedMemorySize, SMEM_TC);
    dim3 tgrid(OUT_DIM / TN_TC, B_TOT / TM_TC);   // (4, 32) = 128 CTAs
    tc_gemm_kernel<<<tgrid, 128, SMEM_TC>>>(out);

    // legacy path (no-op body when the 'a' pass is the one loaded)
    cudaFuncSetAttribute(fb_gemm_kernel,
                         cudaFuncAttributeMaxDynamicSharedMemorySize, SMEM_FB);
    dim3 fgrid(OUT_DIM / TN_FB, B_TOT / TM_FB);   // (8, 16) = 128 CTAs
    fb_gemm_kernel<<<fgrid, 256, SMEM_FB>>>(out);
}